// round 9
// baseline (speedup 1.0000x reference)
#include <cuda_runtime.h>
#include <cuda_bf16.h>
#include <mma.h>
#include <cstdint>

using namespace nvcuda;
typedef __nv_bfloat16 bf16;

// Problem constants
#define Bc   2
#define Lc   2048
#define Dc   1024
#define Hc   16
#define DKc  64
#define NEGF (-3.4028235e38f)

#define NEL (Bc * Lc * Dc)     // 4,194,304
#define NW  (Dc * Dc)          // 1,048,576
#define KK  1024

// ---------------------------------------------------------------------------
// Scratch (device globals — no allocation allowed)
// ---------------------------------------------------------------------------
__device__ bf16 g_qh[NEL], g_ql[NEL], g_kh[NEL], g_kl[NEL], g_vh[NEL], g_vl[NEL];
__device__ bf16 g_wqh[NW], g_wql[NW], g_wkh[NW], g_wkl[NW];
__device__ bf16 g_wvh[NW], g_wvl[NW], g_woh[NW], g_wol[NW];
__device__ bf16 g_Qh[NEL], g_Ql[NEL], g_Kh[NEL], g_Kl[NEL], g_Vh[NEL], g_Vl[NEL];
__device__ bf16 g_aoh[NEL], g_aol[NEL];

// ---------------------------------------------------------------------------
// Split fp32 -> bf16 hi + bf16 lo
// ---------------------------------------------------------------------------
__device__ __forceinline__ void split1(float x, bf16& h, bf16& l) {
    h = __float2bfloat16_rn(x);
    l = __float2bfloat16_rn(x - __bfloat162float(h));
}

__global__ void split_bf16(const float* __restrict__ x, bf16* __restrict__ hi,
                           bf16* __restrict__ lo, int n)
{
    int i = (blockIdx.x * blockDim.x + threadIdx.x) * 4;
    if (i >= n) return;
    float4 v = *(const float4*)(x + i);
    bf16 h0, h1, h2, h3, l0, l1, l2, l3;
    split1(v.x, h0, l0); split1(v.y, h1, l1);
    split1(v.z, h2, l2); split1(v.w, h3, l3);
    __nv_bfloat162* H = (__nv_bfloat162*)(hi + i);
    __nv_bfloat162* L = (__nv_bfloat162*)(lo + i);
    H[0] = __nv_bfloat162(h0, h1); H[1] = __nv_bfloat162(h2, h3);
    L[0] = __nv_bfloat162(l0, l1); L[1] = __nv_bfloat162(l2, l3);
}

// ---------------------------------------------------------------------------
// cp.async helpers
// ---------------------------------------------------------------------------
__device__ __forceinline__ void cp16(unsigned dst, const void* src) {
    asm volatile("cp.async.cg.shared.global [%0], [%1], 16;" :: "r"(dst), "l"(src));
}
#define CP_COMMIT() asm volatile("cp.async.commit_group;")
#define CP_WAIT(n)  asm volatile("cp.async.wait_group %0;" :: "n"(n))

typedef wmma::fragment<wmma::matrix_a, 16, 16, 16, bf16, wmma::row_major> FragA;
typedef wmma::fragment<wmma::matrix_b, 16, 16, 16, bf16, wmma::col_major> FragBc;
typedef wmma::fragment<wmma::matrix_b, 16, 16, 16, bf16, wmma::row_major> FragBr;
typedef wmma::fragment<wmma::accumulator, 16, 16, 16, float> FragC;

// ---------------------------------------------------------------------------
// bf16x3 GEMM  C[m][n] = sum_d A[m][d] * Bw[n][d]   (NT)
// 128x128x32 tile, 8 warps (4x2), warp 32x64, double-buffered cp.async,
// j-pipelined B-fragment loads. scatter==1: emit hi/lo bf16 into [b,h,l,dk].
// ---------------------------------------------------------------------------
#define SAL    40            // smem row stride (bf16 elems)
#define AB_EL  (128 * SAL)
#define STG_EL (4 * AB_EL)
#define GEMM_SMEM (2 * STG_EL * 2)   // 81,920 bytes

__global__ __launch_bounds__(256)
void gemm_bf16x3(const bf16* __restrict__ Ah, const bf16* __restrict__ Al,
                 const bf16* __restrict__ Bh, const bf16* __restrict__ Bl,
                 float* __restrict__ C, bf16* __restrict__ Ch, bf16* __restrict__ Cl,
                 int scatter)
{
    extern __shared__ char dsm[];
    bf16*  smem = (bf16*)dsm;
    float* epi  = (float*)dsm;
    const unsigned sbase = (unsigned)__cvta_generic_to_shared(dsm);

    const int t    = threadIdx.x;
    const int warp = t >> 5;
    const int wm   = warp >> 1;
    const int wn   = warp & 1;
    const int m0   = blockIdx.y * 128;
    const int n0   = blockIdx.x * 128;

    const bf16* gsrc[4] = { Ah + (size_t)m0 * KK, Al + (size_t)m0 * KK,
                            Bh + (size_t)n0 * KK, Bl + (size_t)n0 * KK };

    FragC acc[2][4];
#pragma unroll
    for (int i = 0; i < 2; ++i)
#pragma unroll
        for (int j = 0; j < 4; ++j) wmma::fill_fragment(acc[i][j], 0.0f);

    auto prefetch = [&](int s, int kb) {
#pragma unroll
        for (int a = 0; a < 4; ++a)
#pragma unroll
            for (int rep = 0; rep < 2; ++rep) {
                int chunk = t + rep * 256;
                int row = chunk >> 2, seg = chunk & 3;
                cp16(sbase + (unsigned)(s * STG_EL + a * AB_EL + row * SAL + seg * 8) * 2,
                     gsrc[a] + (size_t)row * KK + kb + seg * 8);
            }
        CP_COMMIT();
    };

    prefetch(0, 0);

    for (int it = 0; it < KK / 32; ++it) {
        int s = it & 1;
        if (it + 1 < KK / 32) { prefetch(s ^ 1, (it + 1) * 32); CP_WAIT(1); }
        else                  { CP_WAIT(0); }
        __syncthreads();

        const bf16* sAh = smem + s * STG_EL;
        const bf16* sAl = sAh + AB_EL;
        const bf16* sBh = sAl + AB_EL;
        const bf16* sBl = sBh + AB_EL;

#pragma unroll
        for (int ks = 0; ks < 32; ks += 16) {
            FragA ah[2], al[2];
#pragma unroll
            for (int i = 0; i < 2; ++i) {
                wmma::load_matrix_sync(ah[i], &sAh[(wm * 32 + i * 16) * SAL + ks], SAL);
                wmma::load_matrix_sync(al[i], &sAl[(wm * 32 + i * 16) * SAL + ks], SAL);
            }

            FragBc b0h, b0l, b1h, b1l;
            wmma::load_matrix_sync(b0h, &sBh[(wn * 64 + 0 * 16) * SAL + ks], SAL);
            wmma::load_matrix_sync(b0l, &sBl[(wn * 64 + 0 * 16) * SAL + ks], SAL);

            // j-pipelined: prefetch j+1 B frags while MMAing j
#define GMMA_J(J, BH, BL) \
            { \
                wmma::mma_sync(acc[0][J], al[0], BH, acc[0][J]); \
                wmma::mma_sync(acc[0][J], ah[0], BL, acc[0][J]); \
                wmma::mma_sync(acc[0][J], ah[0], BH, acc[0][J]); \
                wmma::mma_sync(acc[1][J], al[1], BH, acc[1][J]); \
                wmma::mma_sync(acc[1][J], ah[1], BL, acc[1][J]); \
                wmma::mma_sync(acc[1][J], ah[1], BH, acc[1][J]); \
            }
            wmma::load_matrix_sync(b1h, &sBh[(wn * 64 + 1 * 16) * SAL + ks], SAL);
            wmma::load_matrix_sync(b1l, &sBl[(wn * 64 + 1 * 16) * SAL + ks], SAL);
            GMMA_J(0, b0h, b0l);
            wmma::load_matrix_sync(b0h, &sBh[(wn * 64 + 2 * 16) * SAL + ks], SAL);
            wmma::load_matrix_sync(b0l, &sBl[(wn * 64 + 2 * 16) * SAL + ks], SAL);
            GMMA_J(1, b1h, b1l);
            wmma::load_matrix_sync(b1h, &sBh[(wn * 64 + 3 * 16) * SAL + ks], SAL);
            wmma::load_matrix_sync(b1l, &sBl[(wn * 64 + 3 * 16) * SAL + ks], SAL);
            GMMA_J(2, b0h, b0l);
            GMMA_J(3, b1h, b1l);
#undef GMMA_J
        }
        __syncthreads();
    }

    // epilogue via fp32 smem buffer (stride 132)
    __syncthreads();
#pragma unroll
    for (int i = 0; i < 2; ++i)
#pragma unroll
        for (int j = 0; j < 4; ++j)
            wmma::store_matrix_sync(&epi[(wm * 32 + i * 16) * 132 + wn * 64 + j * 16],
                                    acc[i][j], 132, wmma::mem_row_major);
    __syncthreads();

#pragma unroll
    for (int f = 0; f < 16; ++f) {
        int idx = t + f * 256;
        int row = idx >> 5, c4 = idx & 31;
        float4 v = *(float4*)&epi[row * 132 + c4 * 4];
        int m = m0 + row, n = n0 + c4 * 4;
        if (!scatter) {
            *(float4*)&C[(size_t)m * Dc + n] = v;
        } else {
            int b = m >> 11, l = m & (Lc - 1);
            int h = n >> 6,  dk = n & 63;
            size_t o = (((size_t)b * Hc + h) * Lc + l) * DKc + dk;
            bf16 h0, h1, h2, h3, l0, l1, l2, l3;
            split1(v.x, h0, l0); split1(v.y, h1, l1);
            split1(v.z, h2, l2); split1(v.w, h3, l3);
            *(__nv_bfloat162*)&Ch[o]     = __nv_bfloat162(h0, h1);
            *(__nv_bfloat162*)&Ch[o + 2] = __nv_bfloat162(h2, h3);
            *(__nv_bfloat162*)&Cl[o]     = __nv_bfloat162(l0, l1);
            *(__nv_bfloat162*)&Cl[o + 2] = __nv_bfloat162(l2, l3);
        }
    }
}

// ---------------------------------------------------------------------------
// Fused attention: block = one (b,h), 16 queries. Fragment-prefetch pipelined.
// ---------------------------------------------------------------------------
#define SP   2052
#define PLOP 2056
#define RST  72
#define ATT_SMEM (16 * SP * 4 + 16 * PLOP * 2 + 2 * 16 * RST * 4)

__global__ __launch_bounds__(256)
void attn_entmax_kernel(const bf16* __restrict__ Qh, const bf16* __restrict__ Ql,
                        const bf16* __restrict__ Kh, const bf16* __restrict__ Kl,
                        const bf16* __restrict__ Vh, const bf16* __restrict__ Vl,
                        const int* __restrict__ maskp,
                        bf16* __restrict__ AOh, bf16* __restrict__ AOl)
{
    extern __shared__ float sm[];
    float* Ssh  = sm;
    bf16*  PloS = (bf16*)(sm + 16 * SP);
    float* Rsh  = (float*)((char*)PloS + 16 * PLOP * 2);

    const int t    = threadIdx.x;
    const int warp = t >> 5;
    const int lane = t & 31;
    const int q0   = blockIdx.x * 16;
    const int h    = blockIdx.y;
    const int b    = blockIdx.z;
    const int bh   = b * Hc + h;

    const bf16* Qhg = Qh + ((size_t)bh * Lc + q0) * DKc;
    const bf16* Qlg = Ql + ((size_t)bh * Lc + q0) * DKc;
    const bf16* Khg = Kh + (size_t)bh * Lc * DKc;
    const bf16* Klg = Kl + (size_t)bh * Lc * DKc;
    const bf16* Vhg = Vh + (size_t)bh * Lc * DKc;
    const bf16* Vlg = Vl + (size_t)bh * Lc * DKc;

    // ---- Phase S: S[16 x 2048] = Q K^T (bf16x3, K-frag prefetch pipeline) ----
    {
        FragA aqh[4], aql[4];
#pragma unroll
        for (int kf = 0; kf < 4; ++kf) {
            wmma::load_matrix_sync(aqh[kf], Qhg + kf * 16, DKc);
            wmma::load_matrix_sync(aql[kf], Qlg + kf * 16, DKc);
        }

        FragBc k0h, k0l, k1h, k1l;
        auto ldK = [&](int cc, int kk, FragBc& kh_, FragBc& kl_) {
            size_t base = (size_t)(cc * 128 + warp * 16) * DKc + kk * 16;
            wmma::load_matrix_sync(kh_, Khg + base, DKc);
            wmma::load_matrix_sync(kl_, Klg + base, DKc);
        };
#define SMMA(KF, KH, KL) \
        { wmma::mma_sync(acc, aql[KF], KH, acc); \
          wmma::mma_sync(acc, aqh[KF], KL, acc); \
          wmma::mma_sync(acc, aqh[KF], KH, acc); }

        ldK(0, 0, k0h, k0l);
#pragma unroll 1
        for (int c = 0; c < 16; ++c) {
            FragC acc;
            wmma::fill_fragment(acc, 0.0f);
            int nc = (c < 15) ? c + 1 : 15;
            ldK(c, 1, k1h, k1l);  SMMA(0, k0h, k0l);
            ldK(c, 2, k0h, k0l);  SMMA(1, k1h, k1l);
            ldK(c, 3, k1h, k1l);  SMMA(2, k0h, k0l);
            ldK(nc, 0, k0h, k0l); SMMA(3, k1h, k1l);
            wmma::store_matrix_sync(&Ssh[c * 128 + warp * 16], acc, SP, wmma::mem_row_major);
        }
#undef SMMA
    }
    __syncthreads();

    // ---- mask + scale ----
    {
        const int* mbase = maskp + ((size_t)b * Lc + q0) * Lc;
#pragma unroll 4
        for (int f = t; f < 16 * 512; f += 256) {
            int row = f >> 9, c4 = f & 511;
            float4 s = *(float4*)&Ssh[row * SP + c4 * 4];
            int4  mv = *(const int4*)&mbase[(size_t)row * Lc + c4 * 4];
            s.x = mv.x ? s.x * 0.125f : NEGF;
            s.y = mv.y ? s.y * 0.125f : NEGF;
            s.z = mv.z ? s.z * 0.125f : NEGF;
            s.w = mv.w ? s.w * 0.125f : NEGF;
            *(float4*)&Ssh[row * SP + c4 * 4] = s;
        }
    }
    __syncthreads();

    // ---- entmax15 (Newton on tau), emit P hi/lo bf16 ----
    for (int r = 0; r < 2; ++r) {
        int qi = warp * 2 + r;
        float* Srow = &Ssh[qi * SP];
        float z[64];
        float mx = NEGF;
#pragma unroll
        for (int u = 0; u < 64; ++u) {
            z[u] = Srow[lane + 32 * u];
            mx = fmaxf(mx, z[u]);
        }
#pragma unroll
        for (int off = 16; off; off >>= 1)
            mx = fmaxf(mx, __shfl_xor_sync(0xffffffffu, mx, off));
#pragma unroll
        for (int u = 0; u < 64; ++u) z[u] = (z[u] - mx) * 0.5f;

        float tau = -1.0f;
#pragma unroll 1
        for (int it = 0; it < 8; ++it) {
            float s = 0.f, s1 = 0.f;
#pragma unroll
            for (int u = 0; u < 64; ++u) {
                float d = fmaxf(z[u] - tau, 0.f);
                s  = fmaf(d, d, s);
                s1 += d;
            }
#pragma unroll
            for (int off = 16; off; off >>= 1) {
                s  += __shfl_xor_sync(0xffffffffu, s,  off);
                s1 += __shfl_xor_sync(0xffffffffu, s1, off);
            }
            tau += (s - 1.0f) / (2.0f * s1);
        }
        bf16* ph = (bf16*)Srow;
        bf16* pl = PloS + qi * PLOP;
#pragma unroll
        for (int u = 0; u < 64; ++u) {
            int k = lane + 32 * u;
            float d = fmaxf(z[u] - tau, 0.f);
            float p = d * d;
            bf16 hh, ll;
            split1(p, hh, ll);
            ph[k] = hh;
            pl[k] = ll;
        }
    }
    __syncthreads();

    // ---- Phase PV: out[16 x 64] = P V (bf16x3), prefetch-pipelined ----
    {
        int khalf = warp >> 2;
        int d0    = (warp & 3) * 16;
        const bf16* PhiS = (const bf16*)Ssh;
        FragC acc;
        wmma::fill_fragment(acc, 0.0f);

        FragA p0h, p0l, p1h, p1l;
        FragBr v0h, v0l, v1h, v1l;
        auto ldPV = [&](int kf, FragA& ph_, FragA& pl_, FragBr& vh_, FragBr& vl_) {
            int k0 = khalf * 1024 + kf * 16;
            wmma::load_matrix_sync(ph_, PhiS + k0, 2 * SP);
            wmma::load_matrix_sync(pl_, PloS + k0, PLOP);
            wmma::load_matrix_sync(vh_, Vhg + (size_t)k0 * DKc + d0, DKc);
            wmma::load_matrix_sync(vl_, Vlg + (size_t)k0 * DKc + d0, DKc);
        };
#define PVMMA(PH, PL, VH, VL) \
        { wmma::mma_sync(acc, PL, VH, acc); \
          wmma::mma_sync(acc, PH, VL, acc); \
          wmma::mma_sync(acc, PH, VH, acc); }

        ldPV(0, p0h, p0l, v0h, v0l);
#pragma unroll 1
        for (int kf = 0; kf < 64; kf += 2) {
            ldPV(kf + 1, p1h, p1l, v1h, v1l);
            PVMMA(p0h, p0l, v0h, v0l);
            int nk = (kf + 2 < 64) ? kf + 2 : 63;
            ldPV(nk, p0h, p0l, v0h, v0l);
            PVMMA(p1h, p1l, v1h, v1l);
        }
#undef PVMMA
        wmma::store_matrix_sync(&Rsh[khalf * 16 * RST + d0], acc, RST, wmma::mem_row_major);
    }
    __syncthreads();

    // ---- reduce halves + write AO hi/lo ----
    {
        int qi = t >> 4;
        int c4 = t & 15;
        float4 r0 = *(float4*)&Rsh[qi * RST + c4 * 4];
        float4 r1 = *(float4*)&Rsh[16 * RST + qi * RST + c4 * 4];
        float4 o;
        o.x = r0.x + r1.x; o.y = r0.y + r1.y; o.z = r0.z + r1.z; o.w = r0.w + r1.w;
        size_t base = ((size_t)b * Lc + q0 + qi) * Dc + h * DKc + c4 * 4;
        bf16 h0, h1, h2, h3, l0, l1, l2, l3;
        split1(o.x, h0, l0); split1(o.y, h1, l1);
        split1(o.z, h2, l2); split1(o.w, h3, l3);
        *(__nv_bfloat162*)&AOh[base]     = __nv_bfloat162(h0, h1);
        *(__nv_bfloat162*)&AOh[base + 2] = __nv_bfloat162(h2, h3);
        *(__nv_bfloat162*)&AOl[base]     = __nv_bfloat162(l0, l1);
        *(__nv_bfloat162*)&AOl[base + 2] = __nv_bfloat162(l2, l3);
    }
}

// ---------------------------------------------------------------------------
// Launch
// ---------------------------------------------------------------------------
extern "C" void kernel_launch(void* const* d_in, const int* in_sizes, int n_in,
                              void* d_out, int out_size)
{
    const float* q    = (const float*)d_in[0];
    const float* k    = (const float*)d_in[1];
    const float* v    = (const float*)d_in[2];
    const int*   mask = (const int*)  d_in[3];
    const float* w_q  = (const float*)d_in[4];
    const float* w_k  = (const float*)d_in[5];
    const float* w_v  = (const float*)d_in[6];
    const float* w_o  = (const float*)d_in[7];
    float* out = (float*)d_out;

    bf16 *qh,*ql,*kh,*kl,*vh,*vl;
    bf16 *wqh,*wql,*wkh,*wkl,*wvh,*wvl,*woh,*wol;
    bf16 *Qh,*Ql,*Kh,*Kl,*Vh,*Vl,*aoh,*aol;
    cudaGetSymbolAddress((void**)&qh, g_qh);   cudaGetSymbolAddress((void**)&ql, g_ql);
    cudaGetSymbolAddress((void**)&kh, g_kh);   cudaGetSymbolAddress((void**)&kl, g_kl);
    cudaGetSymbolAddress((void**)&vh, g_vh);   cudaGetSymbolAddress((void**)&vl, g_vl);
    cudaGetSymbolAddress((void**)&wqh, g_wqh); cudaGetSymbolAddress((void**)&wql, g_wql);
    cudaGetSymbolAddress((void**)&wkh, g_wkh); cudaGetSymbolAddress((void**)&wkl, g_wkl);
    cudaGetSymbolAddress((void**)&wvh, g_wvh); cudaGetSymbolAddress((void**)&wvl, g_wvl);
    cudaGetSymbolAddress((void**)&woh, g_woh); cudaGetSymbolAddress((void**)&wol, g_wol);
    cudaGetSymbolAddress((void**)&Qh, g_Qh);   cudaGetSymbolAddress((void**)&Ql, g_Ql);
    cudaGetSymbolAddress((void**)&Kh, g_Kh);   cudaGetSymbolAddress((void**)&Kl, g_Kl);
    cudaGetSymbolAddress((void**)&Vh, g_Vh);   cudaGetSymbolAddress((void**)&Vl, g_Vl);
    cudaGetSymbolAddress((void**)&aoh, g_aoh); cudaGetSymbolAddress((void**)&aol, g_aol);

    split_bf16<<<NEL / 1024, 256>>>(q, qh, ql, NEL);
    split_bf16<<<NEL / 1024, 256>>>(k, kh, kl, NEL);
    split_bf16<<<NEL / 1024, 256>>>(v, vh, vl, NEL);
    split_bf16<<<NW / 1024, 256>>>(w_q, wqh, wql, NW);
    split_bf16<<<NW / 1024, 256>>>(w_k, wkh, wkl, NW);
    split_bf16<<<NW / 1024, 256>>>(w_v, wvh, wvl, NW);
    split_bf16<<<NW / 1024, 256>>>(w_o, woh, wol, NW);

    cudaFuncSetAttribute(gemm_bf16x3,
                         cudaFuncAttributeMaxDynamicSharedMemorySize, GEMM_SMEM);
    dim3 gg(Dc / 128, (Bc * Lc) / 128);       // (8, 32)

    gemm_bf16x3<<<gg, 256, GEMM_SMEM>>>(qh, ql, wqh, wql, nullptr, Qh, Ql, 1);
    gemm_bf16x3<<<gg, 256, GEMM_SMEM>>>(kh, kl, wkh, wkl, nullptr, Kh, Kl, 1);
    gemm_bf16x3<<<gg, 256, GEMM_SMEM>>>(vh, vl, wvh, wvl, nullptr, Vh, Vl, 1);

    cudaFuncSetAttribute(attn_entmax_kernel,
                         cudaFuncAttributeMaxDynamicSharedMemorySize, ATT_SMEM);
    attn_entmax_kernel<<<dim3(Lc / 16, Hc, Bc), 256, ATT_SMEM>>>(
        Qh, Ql, Kh, Kl, Vh, Vl, mask, aoh, aol);

    gemm_bf16x3<<<gg, 256, GEMM_SMEM>>>(aoh, aol, woh, wol, out, nullptr, nullptr, 0);
}